// round 5
// baseline (speedup 1.0000x reference)
#include <cuda_runtime.h>
#include <cuda_bf16.h>
#include <cstdint>

// Problem constants
#define B 16
#define S 4096
#define H 768
#define T 2000

__device__ int g_starts[B * T];

// ---------------------------------------------------------------------------
// 256-bit global load/store (sm_100+). 32-byte aligned addresses required.
// ---------------------------------------------------------------------------
__device__ __forceinline__ void ldg256(const float* p, float v[8]) {
    unsigned r0, r1, r2, r3, r4, r5, r6, r7;
    asm("ld.global.v8.b32 {%0,%1,%2,%3,%4,%5,%6,%7}, [%8];"
        : "=r"(r0), "=r"(r1), "=r"(r2), "=r"(r3),
          "=r"(r4), "=r"(r5), "=r"(r6), "=r"(r7)
        : "l"(p));
    v[0] = __uint_as_float(r0); v[1] = __uint_as_float(r1);
    v[2] = __uint_as_float(r2); v[3] = __uint_as_float(r3);
    v[4] = __uint_as_float(r4); v[5] = __uint_as_float(r5);
    v[6] = __uint_as_float(r6); v[7] = __uint_as_float(r7);
}

__device__ __forceinline__ void stg256(float* p, const float v[8]) {
    asm volatile("st.global.v8.b32 [%0], {%1,%2,%3,%4,%5,%6,%7,%8};"
        :: "l"(p),
           "r"(__float_as_uint(v[0])), "r"(__float_as_uint(v[1])),
           "r"(__float_as_uint(v[2])), "r"(__float_as_uint(v[3])),
           "r"(__float_as_uint(v[4])), "r"(__float_as_uint(v[5])),
           "r"(__float_as_uint(v[6])), "r"(__float_as_uint(v[7]))
        : "memory");
}

// ---------------------------------------------------------------------------
// Kernel 1: per-batch exclusive prefix sum over T lengths (shuffle scan).
// ---------------------------------------------------------------------------
__global__ void __launch_bounds__(1024) scan_kernel(const int* __restrict__ lens) {
    const int b    = blockIdx.x;
    const int tid  = threadIdx.x;
    const int lane = tid & 31;
    const int wid  = tid >> 5;

    const int* L = lens + (size_t)b * T;

    const int idx0 = tid * 2;
    int v0 = 0, v1 = 0;
    if (idx0 + 1 < T) {
        int2 v = *(const int2*)(L + idx0);
        v0 = v.x; v1 = v.y;
    } else if (idx0 < T) {
        v0 = L[idx0];
    }
    int tsum = v0 + v1;

    int incl = tsum;
#pragma unroll
    for (int off = 1; off < 32; off <<= 1) {
        int n = __shfl_up_sync(0xffffffffu, incl, off);
        if (lane >= off) incl += n;
    }
    const int excl = incl - tsum;

    __shared__ int warpsums[32];
    if (lane == 31) warpsums[wid] = incl;
    __syncthreads();

    if (wid == 0) {
        int w = warpsums[lane];
        int wi = w;
#pragma unroll
        for (int off = 1; off < 32; off <<= 1) {
            int n = __shfl_up_sync(0xffffffffu, wi, off);
            if (lane >= off) wi += n;
        }
        warpsums[lane] = wi - w;
    }
    __syncthreads();

    const int base = warpsums[wid] + excl;
    if (idx0 + 1 < T) {
        *(int2*)(g_starts + (size_t)b * T + idx0) = make_int2(base, base + v0);
    } else if (idx0 < T) {
        g_starts[(size_t)b * T + idx0] = base;
    }
}

// ---------------------------------------------------------------------------
// Kernel 2: one warp per token. 256-bit loads/stores: 3 per row per lane
// (32 lanes x 8 floats x 3 = 768). len in {0,1,2}.
// ---------------------------------------------------------------------------
__global__ void __launch_bounds__(256) pool_kernel(
    const float* __restrict__ hs,      // [B, S, H]
    const int*   __restrict__ lens,    // [B, T]
    float*       __restrict__ out)     // [B, T, H]
{
    const int warp = (blockIdx.x * blockDim.x + threadIdx.x) >> 5;
    const int lane = threadIdx.x & 31;
    if (warp >= B * T) return;

    const int b     = warp / T;
    const int len   = lens[warp];
    const int start = g_starts[warp];

    float* dst = out + (size_t)warp * H;

    if (len == 0) {
        const float z[8] = {0.f, 0.f, 0.f, 0.f, 0.f, 0.f, 0.f, 0.f};
#pragma unroll
        for (int k = 0; k < 3; k++) stg256(dst + lane * 8 + 256 * k, z);
        return;
    }

    // First covered position is 1 + start (1-based positions)
    const size_t row0 = (size_t)b * S + 1 + start;
    const float* src0 = hs + row0 * H;

    float acc[3][8];
#pragma unroll
    for (int k = 0; k < 3; k++) ldg256(src0 + lane * 8 + 256 * k, acc[k]);

    if (len == 2) {
        const float* src1 = src0 + H;
        float v[3][8];
#pragma unroll
        for (int k = 0; k < 3; k++) ldg256(src1 + lane * 8 + 256 * k, v[k]);
#pragma unroll
        for (int k = 0; k < 3; k++)
#pragma unroll
            for (int j = 0; j < 8; j++) acc[k][j] = (acc[k][j] + v[k][j]) * 0.5f;
    }

#pragma unroll
    for (int k = 0; k < 3; k++) stg256(dst + lane * 8 + 256 * k, acc[k]);
}

// ---------------------------------------------------------------------------
extern "C" void kernel_launch(void* const* d_in, const int* in_sizes, int n_in,
                              void* d_out, int out_size)
{
    const float* hs   = (const float*)d_in[0];   // [B,S,H] fp32
    const int*   lens = (const int*)d_in[1];     // [B,T] int32
    float*       out  = (float*)d_out;           // [B,T,H] fp32

    (void)in_sizes; (void)n_in; (void)out_size;

    scan_kernel<<<B, 1024>>>(lens);

    const int n_warps = B * T;                    // one warp per token
    const int blocks  = (n_warps * 32 + 255) / 256;
    pool_kernel<<<blocks, 256>>>(hs, lens, out);
}

// round 6
// speedup vs baseline: 1.0103x; 1.0103x over previous
#include <cuda_runtime.h>
#include <cuda_bf16.h>
#include <cstdint>

// Problem constants
#define B 16
#define S 4096
#define H 768
#define T 2000

// Packed per-token descriptor: start | (len << 16). start <= 4000, len in {0,1,2}.
__device__ int g_desc[B * T];

// ---------------------------------------------------------------------------
// Kernel 1: per-batch exclusive prefix sum over T lengths (shuffle scan),
// writing packed (start, len) descriptors.
// ---------------------------------------------------------------------------
__global__ void __launch_bounds__(1024) scan_kernel(const int* __restrict__ lens) {
    const int b    = blockIdx.x;
    const int tid  = threadIdx.x;
    const int lane = tid & 31;
    const int wid  = tid >> 5;

    const int* L = lens + (size_t)b * T;

    const int idx0 = tid * 2;
    int v0 = 0, v1 = 0;
    if (idx0 + 1 < T) {
        int2 v = *(const int2*)(L + idx0);
        v0 = v.x; v1 = v.y;
    } else if (idx0 < T) {
        v0 = L[idx0];
    }
    int tsum = v0 + v1;

    int incl = tsum;
#pragma unroll
    for (int off = 1; off < 32; off <<= 1) {
        int n = __shfl_up_sync(0xffffffffu, incl, off);
        if (lane >= off) incl += n;
    }
    const int excl = incl - tsum;

    __shared__ int warpsums[32];
    if (lane == 31) warpsums[wid] = incl;
    __syncthreads();

    if (wid == 0) {
        int w = warpsums[lane];
        int wi = w;
#pragma unroll
        for (int off = 1; off < 32; off <<= 1) {
            int n = __shfl_up_sync(0xffffffffu, wi, off);
            if (lane >= off) wi += n;
        }
        warpsums[lane] = wi - w;
    }
    __syncthreads();

    const int base = warpsums[wid] + excl;
    if (idx0 + 1 < T) {
        int2 d;
        d.x = base | (v0 << 16);
        d.y = (base + v0) | (v1 << 16);
        *(int2*)(g_desc + (size_t)b * T + idx0) = d;
    } else if (idx0 < T) {
        g_desc[(size_t)b * T + idx0] = base | (v0 << 16);
    }
}

// ---------------------------------------------------------------------------
// Kernel 2: HALF a token per warp. Each lane handles 3 float4 (48B);
// 64 lanes (2 warps) cover the 768-float row. One index load per warp.
// ---------------------------------------------------------------------------
__global__ void __launch_bounds__(256) pool_kernel(
    const float* __restrict__ hs,      // [B, S, H]
    float*       __restrict__ out)     // [B, T, H]
{
    const int gwarp = (blockIdx.x * blockDim.x + threadIdx.x) >> 5;
    const int lane  = threadIdx.x & 31;
    const int tok   = gwarp >> 1;            // token index
    const int half  = gwarp & 1;             // which half of the row
    if (tok >= B * T) return;

    const int desc  = __ldg(g_desc + tok);
    const int start = desc & 0xFFFF;
    const int len   = desc >> 16;
    const int b     = tok / T;

    // half-row offset in float4 units: 96 float4 per half
    const int f4off = half * 96 + lane;

    float4* dst = (float4*)(out + (size_t)tok * H);

    if (len == 0) {
        const float4 z = make_float4(0.f, 0.f, 0.f, 0.f);
#pragma unroll
        for (int k = 0; k < 3; k++) dst[f4off + 32 * k] = z;
        return;
    }

    // First covered position is 1 + start (1-based positions)
    const size_t row0 = (size_t)b * S + 1 + start;
    const float4* src0 = (const float4*)(hs + row0 * H);

    float4 acc[3];
#pragma unroll
    for (int k = 0; k < 3; k++) acc[k] = src0[f4off + 32 * k];

    if (len == 2) {
        const float4* src1 = src0 + (H / 4);
#pragma unroll
        for (int k = 0; k < 3; k++) {
            float4 v = src1[f4off + 32 * k];
            acc[k].x = (acc[k].x + v.x) * 0.5f;
            acc[k].y = (acc[k].y + v.y) * 0.5f;
            acc[k].z = (acc[k].z + v.z) * 0.5f;
            acc[k].w = (acc[k].w + v.w) * 0.5f;
        }
    }

#pragma unroll
    for (int k = 0; k < 3; k++) dst[f4off + 32 * k] = acc[k];
}

// ---------------------------------------------------------------------------
extern "C" void kernel_launch(void* const* d_in, const int* in_sizes, int n_in,
                              void* d_out, int out_size)
{
    const float* hs   = (const float*)d_in[0];   // [B,S,H] fp32
    const int*   lens = (const int*)d_in[1];     // [B,T] int32
    float*       out  = (float*)d_out;           // [B,T,H] fp32

    (void)in_sizes; (void)n_in; (void)out_size;

    scan_kernel<<<B, 1024>>>(lens);

    // two warps per token: B*T*2 warps, 8 warps (256 threads) per block
    const int n_warps = B * T * 2;               // 64000
    const int blocks  = n_warps / 8;             // 8000
    pool_kernel<<<blocks, 256>>>(hs, out);
}